// round 6
// baseline (speedup 1.0000x reference)
#include <cuda_runtime.h>
#include <cuda_fp16.h>

#define DIM 32
#define NODES_MAX 100000
#define EDGES_MAX 3200000
#define SCAN_BLK 1024
#define NB_MAX 128   // ceil(100000/1024)=98

// ---------------- scratch (device globals; no allocation allowed) ------------
// Invariant: g_deg all-zero and g_pool all-zero at entry to kernel_launch
// (zero-initialized at load; k_scan1/k_head restore them every call).
__device__ __half g_p0[NODES_MAX * DIM];
__device__ __half g_p1[NODES_MAX * DIM];
__device__ int    g_deg[NODES_MAX];
__device__ int    g_row[NODES_MAX + 1];
__device__ int    g_wcur[NODES_MAX];
__device__ int    g_ssrc[EDGES_MAX];
__device__ int    g_bsum[NB_MAX];
__device__ float  g_pool[DIM];

// ---------------- CSR build --------------------------------------------------
__global__ void k_hist(const int* __restrict__ dst, int n_edges) {
    int stride = gridDim.x * blockDim.x;
    for (int i = blockIdx.x * blockDim.x + threadIdx.x; i < n_edges; i += stride)
        atomicAdd(&g_deg[__ldg(&dst[i])], 1);
}

__global__ void k_scan1(int n_nodes) {
    __shared__ int s[SCAN_BLK];
    int tid = threadIdx.x;
    int i = blockIdx.x * SCAN_BLK + tid;
    int v = 0;
    if (i < n_nodes) { v = g_deg[i]; g_deg[i] = 0; }
    s[tid] = v;
    __syncthreads();
    for (int off = 1; off < SCAN_BLK; off <<= 1) {
        int t = (tid >= off) ? s[tid - off] : 0;
        __syncthreads();
        s[tid] += t;
        __syncthreads();
    }
    if (i < n_nodes) g_row[i] = s[tid] - v;  // local exclusive
    if (tid == SCAN_BLK - 1) g_bsum[blockIdx.x] = s[tid];
}

__global__ void k_scan3(int n_nodes, int n_edges, int nb) {
    __shared__ int sb[NB_MAX];
    __shared__ int sex[NB_MAX];
    int tid = threadIdx.x;
    int v = 0;
    if (tid < NB_MAX) {
        v = (tid < nb) ? g_bsum[tid] : 0;
        sb[tid] = v;
    }
    __syncthreads();
    for (int off = 1; off < NB_MAX; off <<= 1) {
        int t = 0;
        if (tid < NB_MAX && tid >= off) t = sb[tid - off];
        __syncthreads();
        if (tid < NB_MAX) sb[tid] += t;
        __syncthreads();
    }
    if (tid < NB_MAX) sex[tid] = sb[tid] - v;  // exclusive
    __syncthreads();

    int stride = gridDim.x * blockDim.x;
    int gid = blockIdx.x * blockDim.x + tid;
    for (int i = gid; i < n_nodes; i += stride) {
        int r = g_row[i] + sex[i / SCAN_BLK];
        g_row[i] = r;
        g_wcur[i] = r;
    }
    if (gid == 0) g_row[n_nodes] = n_edges;
}

__global__ void k_fill(const int* __restrict__ src, const int* __restrict__ dst,
                       int n_edges) {
    int stride = gridDim.x * blockDim.x;
    for (int i = blockIdx.x * blockDim.x + threadIdx.x; i < n_edges; i += stride) {
        int pos = atomicAdd(&g_wcur[__ldg(&dst[i])], 1);
        g_ssrc[pos] = __ldg(&src[i]);
    }
}

// ---------------- input projection: p0 = x @ w1a (half output) ---------------
__global__ void k_proj(const float* __restrict__ x, const float* __restrict__ w1a,
                       int n_nodes, int in_dim) {
    __shared__ float ws[96 * DIM];
    for (int i = threadIdx.x; i < in_dim * DIM; i += blockDim.x) ws[i] = w1a[i];
    __syncthreads();
    int lane = threadIdx.x & 31;
    int warp = (blockIdx.x * blockDim.x + threadIdx.x) >> 5;
    int nwarp = (gridDim.x * blockDim.x) >> 5;
    for (int n = warp; n < n_nodes; n += nwarp) {
        const float* xr = x + (size_t)n * in_dim;
        float xv0 = (lane < in_dim) ? __ldg(&xr[lane]) : 0.0f;
        float xv1 = (32 + lane < in_dim) ? __ldg(&xr[32 + lane]) : 0.0f;
        float xv2 = (64 + lane < in_dim) ? __ldg(&xr[64 + lane]) : 0.0f;
        float acc = 0.0f;
        int k = 0;
        for (; k < min(in_dim, 32); k++)
            acc = fmaf(__shfl_sync(0xffffffffu, xv0, k), ws[k * DIM + lane], acc);
        for (; k < min(in_dim, 64); k++)
            acc = fmaf(__shfl_sync(0xffffffffu, xv1, k - 32), ws[k * DIM + lane], acc);
        for (; k < in_dim; k++)
            acc = fmaf(__shfl_sync(0xffffffffu, xv2, k - 64), ws[k * DIM + lane], acc);
        g_p0[n * DIM + lane] = __float2half(acc);
    }
}

// ---------------- fused GIN layer: 2 nodes/warp over combined CSR range ------
// Warp handles consecutive nodes n0=2w, n1=2w+1. Their edge ranges are adjacent
// in CSR: [beg,mid) and [mid,end). One gather loop walks [beg,end) with 8
// independent 4-edge warp-loads per 32-edge batch; each value is routed to the
// right node's accumulators via two branch-free {0,1} masks.
template <bool LAST>
__global__ void __launch_bounds__(256)
k_layer(const __half* __restrict__ p_in, __half* __restrict__ p_out,
        const float* __restrict__ Wb, const float* __restrict__ Bbv,
        const float* __restrict__ Bav, const float* __restrict__ Wanext,
        int n_nodes) {
    __shared__ float s_wb[DIM * DIM];
    __shared__ float s_wa[DIM * DIM];
    for (int i = threadIdx.x; i < DIM * DIM; i += blockDim.x) {
        s_wb[i] = Wb[i];
        if (!LAST) s_wa[i] = Wanext[i];
    }
    __syncthreads();

    const uint2* __restrict__ pu = (const uint2*)p_in;  // row = 8 uint2
    int lane = threadIdx.x & 31;
    int quad = lane >> 3;    // which of 4 edges this lane serves in a load
    int fq   = lane & 7;     // feature-quad: features 4fq .. 4fq+3
    float4 ba4 = __ldg(&((const float4*)Bav)[fq]);
    float bbv = Bbv[lane];

    int warp = (blockIdx.x * blockDim.x + threadIdx.x) >> 5;
    int nwarp = (gridDim.x * blockDim.x) >> 5;
    float pool = 0.0f;

    for (int n0 = 2 * warp; n0 < n_nodes; n0 += 2 * nwarp) {
        int n1 = n0 + 1;
        bool has1 = (n1 < n_nodes);
        int beg = g_row[n0];
        int mid = g_row[n0 + 1];
        int end = has1 ? g_row[n0 + 2] : mid;

        // self rows in flight early (n1 clamped; masked at use)
        uint2 sv0 = pu[n0 * 8 + fq];
        uint2 sv1 = pu[(has1 ? n1 : n0) * 8 + fq];

        // node-0 accumulators
        float b0x = 0.f, b0y = 0.f, b0z = 0.f, b0w = 0.f;
        float b1x = 0.f, b1y = 0.f, b1z = 0.f, b1w = 0.f;
        float b2x = 0.f, b2y = 0.f, b2z = 0.f, b2w = 0.f;
        float b3x = 0.f, b3y = 0.f, b3z = 0.f, b3w = 0.f;
        // node-1 accumulators
        float c0x = 0.f, c0y = 0.f, c0z = 0.f, c0w = 0.f;
        float c1x = 0.f, c1y = 0.f, c1z = 0.f, c1w = 0.f;
        float c2x = 0.f, c2y = 0.f, c2z = 0.f, c2w = 0.f;
        float c3x = 0.f, c3y = 0.f, c3z = 0.f, c3w = 0.f;

        int lim = end - 1;
        for (int base = beg; base < end; base += 32) {
#define GATHER(J, BX, BY, BZ, BW, CX, CY, CZ, CW)                              \
            {                                                                  \
                int pos = base + 4 * (J) + quad;                               \
                int s = __ldg(&g_ssrc[min(pos, lim)]);                         \
                float m0 = (pos < mid) ? 1.0f : 0.0f;                          \
                float m1 = (pos >= mid && pos < end) ? 1.0f : 0.0f;            \
                uint2 v = pu[s * 8 + fq];                                      \
                float2 lo = __half22float2(*(__half2*)&v.x);                   \
                float2 hi = __half22float2(*(__half2*)&v.y);                   \
                BX = fmaf(m0, lo.x, BX); BY = fmaf(m0, lo.y, BY);              \
                BZ = fmaf(m0, hi.x, BZ); BW = fmaf(m0, hi.y, BW);              \
                CX = fmaf(m1, lo.x, CX); CY = fmaf(m1, lo.y, CY);              \
                CZ = fmaf(m1, hi.x, CZ); CW = fmaf(m1, hi.y, CW);              \
            }
            GATHER(0, b0x, b0y, b0z, b0w, c0x, c0y, c0z, c0w)
            GATHER(1, b1x, b1y, b1z, b1w, c1x, c1y, c1z, c1w)
            GATHER(2, b2x, b2y, b2z, b2w, c2x, c2y, c2z, c2w)
            GATHER(3, b3x, b3y, b3z, b3w, c3x, c3y, c3z, c3w)
            GATHER(4, b0x, b0y, b0z, b0w, c0x, c0y, c0z, c0w)
            GATHER(5, b1x, b1y, b1z, b1w, c1x, c1y, c1z, c1w)
            GATHER(6, b2x, b2y, b2z, b2w, c2x, c2y, c2z, c2w)
            GATHER(7, b3x, b3y, b3z, b3w, c3x, c3y, c3z, c3w)
#undef GATHER
        }

        // reduce the 4 slot-groups, then the 4 quads (lanes l, l^8, l^16, l^24)
        float t0 = (b0x + b1x) + (b2x + b3x);
        float t1 = (b0y + b1y) + (b2y + b3y);
        float t2 = (b0z + b1z) + (b2z + b3z);
        float t3 = (b0w + b1w) + (b2w + b3w);
        float r0 = (c0x + c1x) + (c2x + c3x);
        float r1 = (c0y + c1y) + (c2y + c3y);
        float r2 = (c0z + c1z) + (c2z + c3z);
        float r3 = (c0w + c1w) + (c2w + c3w);
#pragma unroll
        for (int d = 8; d <= 16; d <<= 1) {
            t0 += __shfl_xor_sync(0xffffffffu, t0, d);
            t1 += __shfl_xor_sync(0xffffffffu, t1, d);
            t2 += __shfl_xor_sync(0xffffffffu, t2, d);
            t3 += __shfl_xor_sync(0xffffffffu, t3, d);
            r0 += __shfl_xor_sync(0xffffffffu, r0, d);
            r1 += __shfl_xor_sync(0xffffffffu, r1, d);
            r2 += __shfl_xor_sync(0xffffffffu, r2, d);
            r3 += __shfl_xor_sync(0xffffffffu, r3, d);
        }

        float2 s0lo = __half22float2(*(__half2*)&sv0.x);
        float2 s0hi = __half22float2(*(__half2*)&sv0.y);
        float2 s1lo = __half22float2(*(__half2*)&sv1.x);
        float2 s1hi = __half22float2(*(__half2*)&sv1.y);
        t0 = fmaxf(t0 + s0lo.x + ba4.x, 0.0f);
        t1 = fmaxf(t1 + s0lo.y + ba4.y, 0.0f);
        t2 = fmaxf(t2 + s0hi.x + ba4.z, 0.0f);
        t3 = fmaxf(t3 + s0hi.y + ba4.w, 0.0f);
        r0 = fmaxf(r0 + s1lo.x + ba4.x, 0.0f);
        r1 = fmaxf(r1 + s1lo.y + ba4.y, 0.0f);
        r2 = fmaxf(r2 + s1hi.x + ba4.z, 0.0f);
        r3 = fmaxf(r3 + s1hi.y + ba4.w, 0.0f);

        // two independent MLPs (ILP): u_j = relu(sum_k t_k Wb[k][j] + Bb[j])
        float u0 = bbv, u1 = bbv;
#pragma unroll
        for (int f = 0; f < 8; f++) {
            float a0 = __shfl_sync(0xffffffffu, t0, f);
            float a1 = __shfl_sync(0xffffffffu, t1, f);
            float a2 = __shfl_sync(0xffffffffu, t2, f);
            float a3 = __shfl_sync(0xffffffffu, t3, f);
            float d0 = __shfl_sync(0xffffffffu, r0, f);
            float d1 = __shfl_sync(0xffffffffu, r1, f);
            float d2 = __shfl_sync(0xffffffffu, r2, f);
            float d3 = __shfl_sync(0xffffffffu, r3, f);
            u0 = fmaf(a0, s_wb[(4 * f + 0) * DIM + lane], u0);
            u1 = fmaf(d0, s_wb[(4 * f + 0) * DIM + lane], u1);
            u0 = fmaf(a1, s_wb[(4 * f + 1) * DIM + lane], u0);
            u1 = fmaf(d1, s_wb[(4 * f + 1) * DIM + lane], u1);
            u0 = fmaf(a2, s_wb[(4 * f + 2) * DIM + lane], u0);
            u1 = fmaf(d2, s_wb[(4 * f + 2) * DIM + lane], u1);
            u0 = fmaf(a3, s_wb[(4 * f + 3) * DIM + lane], u0);
            u1 = fmaf(d3, s_wb[(4 * f + 3) * DIM + lane], u1);
        }
        u0 = fmaxf(u0, 0.0f);
        u1 = fmaxf(u1, 0.0f);

        if (!LAST) {
            float o0 = 0.0f, o1 = 0.0f;
#pragma unroll
            for (int k = 0; k < DIM; k++) {
                float w = s_wa[k * DIM + lane];
                o0 = fmaf(__shfl_sync(0xffffffffu, u0, k), w, o0);
                o1 = fmaf(__shfl_sync(0xffffffffu, u1, k), w, o1);
            }
            p_out[n0 * DIM + lane] = __float2half(o0);
            if (has1) p_out[n1 * DIM + lane] = __float2half(o1);
        } else {
            pool += u0 + (has1 ? u1 : 0.0f);
        }
    }

    if (LAST) {
        __shared__ float sp[8][DIM];
        int w = threadIdx.x >> 5;
        sp[w][lane] = pool;
        __syncthreads();
        if (w == 0) {
            float s = 0.0f;
#pragma unroll
            for (int i = 0; i < 8; i++) s += sp[i][lane];
            atomicAdd(&g_pool[lane], s);
        }
    }
}

// ---------------- head: consumes g_pool, then RESETS it for next call --------
__global__ void k_head(const float* __restrict__ fcw, const float* __restrict__ fcb,
                       const float* __restrict__ outw, const float* __restrict__ outb,
                       float* __restrict__ out) {
    __shared__ float g2[DIM];
    __shared__ float gp[DIM];
    int j = threadIdx.x;
    float pv = g_pool[j];
    g_pool[j] = 0.0f;   // restore invariant for next kernel_launch call
    gp[j] = pv;
    __syncwarp();
    float acc = fcb[j];
    for (int k = 0; k < DIM; k++) acc = fmaf(gp[k], fcw[k * DIM + j], acc);
    g2[j] = fmaxf(acc, 0.0f);
    __syncwarp();
    float o = outb[j];
    for (int k = 0; k < DIM; k++) o = fmaf(g2[k], outw[k * DIM + j], o);
    out[j] = o;
}

// ---------------- launch ------------------------------------------------------
extern "C" void kernel_launch(void* const* d_in, const int* in_sizes, int n_in,
                              void* d_out, int out_size) {
    const float* x    = (const float*)d_in[0];
    const int*   ei   = (const int*)d_in[1];
    const float* w1a  = (const float*)d_in[2];
    const float* b1a  = (const float*)d_in[3];
    const float* w1b  = (const float*)d_in[4];
    const float* b1b  = (const float*)d_in[5];
    const float* wa   = (const float*)d_in[6];
    const float* ba   = (const float*)d_in[7];
    const float* wb   = (const float*)d_in[8];
    const float* bb   = (const float*)d_in[9];
    const float* fcw  = (const float*)d_in[10];
    const float* fcb  = (const float*)d_in[11];
    const float* outw = (const float*)d_in[12];
    const float* outb = (const float*)d_in[13];

    int in_dim  = in_sizes[2] / DIM;           // w1a is (in_dim, 32)
    int n_nodes = in_sizes[0] / in_dim;        // x is (n, in_dim)
    int n_edges = in_sizes[1] / 2;             // edge_index is (2, E)
    const int* src = ei;
    const int* dst = ei + n_edges;

    __half *p0, *p1;
    cudaGetSymbolAddress((void**)&p0, g_p0);
    cudaGetSymbolAddress((void**)&p1, g_p1);

    // CSR build (g_deg arrives zeroed; scan1 re-zeroes it)
    k_hist<<<2048, 256>>>(dst, n_edges);
    int nb = (n_nodes + SCAN_BLK - 1) / SCAN_BLK;
    k_scan1<<<nb, SCAN_BLK>>>(n_nodes);
    k_scan3<<<256, 256>>>(n_nodes, n_edges, nb);
    k_fill<<<2048, 256>>>(src, dst, n_edges);

    // projection to first-layer pre-aggregation space
    k_proj<<<1024, 256>>>(x, w1a, n_nodes, in_dim);

    // 5 fused GIN layers (double-buffered p); 2 nodes per warp
    k_layer<false><<<2048, 256>>>(p0, p1, w1b, b1b, b1a, wa + 0 * DIM * DIM, n_nodes);
    k_layer<false><<<2048, 256>>>(p1, p0, wb + 0 * DIM * DIM, bb + 0 * DIM, ba + 0 * DIM,
                                  wa + 1 * DIM * DIM, n_nodes);
    k_layer<false><<<2048, 256>>>(p0, p1, wb + 1 * DIM * DIM, bb + 1 * DIM, ba + 1 * DIM,
                                  wa + 2 * DIM * DIM, n_nodes);
    k_layer<false><<<2048, 256>>>(p1, p0, wb + 2 * DIM * DIM, bb + 2 * DIM, ba + 2 * DIM,
                                  wa + 3 * DIM * DIM, n_nodes);
    k_layer<true><<<2048, 256>>>(p0, nullptr, wb + 3 * DIM * DIM, bb + 3 * DIM,
                                 ba + 3 * DIM, nullptr, n_nodes);

    // graph head (also resets g_pool)
    k_head<<<1, 32>>>(fcw, fcb, outw, outb, (float*)d_out);
}